// round 1
// baseline (speedup 1.0000x reference)
#include <cuda_runtime.h>
#include <math.h>

// Problem constants
#define B_   64
#define T_   2048
#define E_   512
#define R_   1024
#define A_   128
#define F_   32
#define KW   31
#define PADW 15

// Extended-K GEMM: K = E (memory) + 62 (im2col of attention_weights_cat) + 2 pad
#define KIM   62
#define KTOT  576
#define KC    16      // k-chunk
#define TT    32      // t-tile per block
#define NCH   8       // T chunks for output GEMV
#define TCH   (T_ / NCH)

// Scratch (device globals; no allocations allowed)
__device__ float g_pq[B_ * A_];
__device__ float g_Wcat[KTOT * A_];
__device__ float g_align[B_ * T_];
__device__ float g_part[NCH * B_ * E_];

// ---------------- packed f32x2 helpers ----------------
__device__ __forceinline__ unsigned long long pack2(float x, float y) {
    unsigned long long r;
    asm("mov.b64 %0, {%1, %2};" : "=l"(r) : "f"(x), "f"(y));
    return r;
}
__device__ __forceinline__ void unpack2(unsigned long long v, float& x, float& y) {
    asm("mov.b64 {%0, %1}, %2;" : "=f"(x), "=f"(y) : "l"(v));
}
__device__ __forceinline__ void ffma2(unsigned long long& d, unsigned long long a, unsigned long long b) {
    asm("fma.rn.f32x2 %0, %1, %2, %0;" : "+l"(d) : "l"(a), "l"(b));
}

// ---------------- pq = attention_hidden @ W_query : (B, A) ----------------
__global__ void k_pq(const float* __restrict__ hid, const float* __restrict__ Wq) {
    __shared__ float sh[R_];
    int b = blockIdx.x, tid = threadIdx.x;
    for (int i = tid; i < R_; i += 128) sh[i] = hid[b * R_ + i];
    __syncthreads();
    float acc = 0.f;
#pragma unroll 8
    for (int r = 0; r < R_; r++) acc += sh[r] * Wq[r * A_ + tid];
    g_pq[b * A_ + tid] = acc;
}

// ------------- Wcat: rows [0,512)=W_memory, [512,574)=conv_w . W_loc, rest 0 -------------
__global__ void k_wcat(const float* __restrict__ Wm, const float* __restrict__ cw,
                       const float* __restrict__ Wl) {
    int row = blockIdx.x;  // 0..575
    int a = threadIdx.x;   // 0..127
    float v = 0.f;
    if (row < E_) {
        v = Wm[row * A_ + a];
    } else if (row < E_ + KIM) {
        int ck = row - E_;
        int c = ck / KW, k = ck - c * KW;
#pragma unroll
        for (int f = 0; f < F_; f++)
            v += cw[f * (2 * KW) + c * KW + k] * Wl[f * A_ + a];
    }
    g_Wcat[row * A_ + a] = v;
}

// ---------------- main fused kernel: energies -> alignments ----------------
// block: 128 threads, tile 32t x 128a, micro-tile 4t x 8a, t packed in f32x2 pairs.
__global__ void __launch_bounds__(128) k_main(const float* __restrict__ mem,
                                              const float* __restrict__ aw,
                                              const int* __restrict__ mask,
                                              const float* __restrict__ vw,
                                              const float* __restrict__ vb) {
    __shared__ unsigned long long sM[KC][TT / 2];   // (mem[t0+2tp][k], mem[t0+2tp+1][k])
    __shared__ unsigned long long sW2[KC][A_];      // (w, w) duplicated pairs
    __shared__ float sPQ[A_];
    __shared__ float sV[A_];

    int b  = blockIdx.y;
    int t0 = blockIdx.x * TT;
    int tid = threadIdx.x;
    sPQ[tid] = g_pq[b * A_ + tid];
    sV[tid]  = vw[tid];

    int ax  = tid & 15;   // 0..15 -> a0 = ax*8
    int tyy = tid >> 4;   // 0..7  -> t local = 4*tyy + {0..3}
    int a0  = ax * 8;

    unsigned long long acc[2][8];
#pragma unroll
    for (int p = 0; p < 2; p++)
#pragma unroll
        for (int j = 0; j < 8; j++) acc[p][j] = 0ull;

    const float* memB = mem + ((size_t)b * T_ + t0) * E_;
    const float* awB  = aw + (size_t)b * 2 * T_;

    int lrow = tid >> 2;   // 0..31 loader row
    int lc4  = tid & 3;    // 0..3 loader col-group

    for (int k0 = 0; k0 < KTOT; k0 += KC) {
        __syncthreads();
        // ---- load mem tile (32 x 16) ----
        if (k0 < E_) {
            float4 v4 = *(const float4*)(memB + (size_t)lrow * E_ + k0 + lc4 * 4);
            float vals[4] = {v4.x, v4.y, v4.z, v4.w};
#pragma unroll
            for (int j = 0; j < 4; j++) {
                int kk = lc4 * 4 + j;
                ((float*)&sM[kk][lrow >> 1])[lrow & 1] = vals[j];
            }
        } else {
            // im2col of attention_weights_cat for location features
#pragma unroll
            for (int j = 0; j < 4; j++) {
                int kk = lc4 * 4 + j;
                int ck = k0 + kk - E_;
                float v = 0.f;
                if (ck < KIM) {
                    int c  = ck / KW;
                    int kp = ck - c * KW;
                    int t  = t0 + lrow + kp - PADW;
                    if (t >= 0 && t < T_) v = awB[c * T_ + t];
                }
                ((float*)&sM[kk][lrow >> 1])[lrow & 1] = v;
            }
        }
        // ---- load W tile (16 x 128), duplicated pairs ----
        {
            const float* wB = g_Wcat + (size_t)k0 * A_;
#pragma unroll
            for (int i = 0; i < 4; i++) {
                int idx = i * 128 + tid;       // 0..511
                int rw = idx >> 5, cw4 = idx & 31;
                float4 v4 = *(const float4*)(wB + rw * A_ + cw4 * 4);
                sW2[rw][cw4 * 4 + 0] = pack2(v4.x, v4.x);
                sW2[rw][cw4 * 4 + 1] = pack2(v4.y, v4.y);
                sW2[rw][cw4 * 4 + 2] = pack2(v4.z, v4.z);
                sW2[rw][cw4 * 4 + 3] = pack2(v4.w, v4.w);
            }
        }
        __syncthreads();
        // ---- compute ----
#pragma unroll
        for (int kk = 0; kk < KC; kk++) {
            unsigned long long m0 = sM[kk][tyy * 2 + 0];
            unsigned long long m1 = sM[kk][tyy * 2 + 1];
            ulonglong2 w01 = *(const ulonglong2*)&sW2[kk][a0 + 0];
            ulonglong2 w23 = *(const ulonglong2*)&sW2[kk][a0 + 2];
            ulonglong2 w45 = *(const ulonglong2*)&sW2[kk][a0 + 4];
            ulonglong2 w67 = *(const ulonglong2*)&sW2[kk][a0 + 6];
            ffma2(acc[0][0], m0, w01.x); ffma2(acc[1][0], m1, w01.x);
            ffma2(acc[0][1], m0, w01.y); ffma2(acc[1][1], m1, w01.y);
            ffma2(acc[0][2], m0, w23.x); ffma2(acc[1][2], m1, w23.x);
            ffma2(acc[0][3], m0, w23.y); ffma2(acc[1][3], m1, w23.y);
            ffma2(acc[0][4], m0, w45.x); ffma2(acc[1][4], m1, w45.x);
            ffma2(acc[0][5], m0, w45.y); ffma2(acc[1][5], m1, w45.y);
            ffma2(acc[0][6], m0, w67.x); ffma2(acc[1][6], m1, w67.x);
            ffma2(acc[0][7], m0, w67.y); ffma2(acc[1][7], m1, w67.y);
        }
    }

    // ---- epilogue: tanh, dot with v, reduce over a, mask ----
    float en[4] = {0.f, 0.f, 0.f, 0.f};
#pragma unroll
    for (int j = 0; j < 8; j++) {
        float vv = sV[a0 + j];
        float pq = sPQ[a0 + j];
        float x, y;
        unpack2(acc[0][j], x, y);
        en[0] += vv * tanhf(x + pq);
        en[1] += vv * tanhf(y + pq);
        unpack2(acc[1][j], x, y);
        en[2] += vv * tanhf(x + pq);
        en[3] += vv * tanhf(y + pq);
    }
#pragma unroll
    for (int off = 8; off >= 1; off >>= 1) {
#pragma unroll
        for (int j = 0; j < 4; j++)
            en[j] += __shfl_xor_sync(0xffffffffu, en[j], off);
    }
    if (ax == 0) {
        float bb = vb[0];
#pragma unroll
        for (int j = 0; j < 4; j++) {
            int t = t0 + tyy * 4 + j;
            float al = en[j] + bb;
            if (mask[b * T_ + t]) al += -1e25f;
            g_align[b * T_ + t] = al;
        }
    }
}

// ---------------- softmax over T per batch -> attention_weights ----------------
__global__ void k_softmax(float* __restrict__ outw) {
    __shared__ float sE[T_];
    __shared__ float red[256];
    int b = blockIdx.x, tid = threadIdx.x;
    float mx = -3.4e38f;
    for (int i = tid; i < T_; i += 256) {
        float v = g_align[b * T_ + i];
        sE[i] = v;
        mx = fmaxf(mx, v);
    }
    red[tid] = mx;
    __syncthreads();
    for (int s = 128; s > 0; s >>= 1) {
        if (tid < s) red[tid] = fmaxf(red[tid], red[tid + s]);
        __syncthreads();
    }
    mx = red[0];
    __syncthreads();
    float sum = 0.f;
    for (int i = tid; i < T_; i += 256) {
        float ev = expf(sE[i] - mx);
        sE[i] = ev;
        sum += ev;
    }
    red[tid] = sum;
    __syncthreads();
    for (int s = 128; s > 0; s >>= 1) {
        if (tid < s) red[tid] += red[tid + s];
        __syncthreads();
    }
    float inv = 1.f / red[0];
    for (int i = tid; i < T_; i += 256) outw[b * T_ + i] = sE[i] * inv;
}

// ---------------- output GEMV: partials over T chunks ----------------
__global__ void k_gemv(const float* __restrict__ mem) {
    __shared__ float sA[TCH];
    int ch = blockIdx.x, b = blockIdx.y, e = threadIdx.x;
    for (int i = e; i < TCH; i += E_) sA[i] = g_align[b * T_ + ch * TCH + i];
    __syncthreads();
    const float* mp = mem + ((size_t)b * T_ + (size_t)ch * TCH) * E_ + e;
    float acc = 0.f;
#pragma unroll 8
    for (int t = 0; t < TCH; t++) acc += sA[t] * mp[(size_t)t * E_];
    g_part[(ch * B_ + b) * E_ + e] = acc;
}

__global__ void k_reduce(float* __restrict__ outa) {
    int b = blockIdx.x, e = threadIdx.x;
    float s = 0.f;
#pragma unroll
    for (int ch = 0; ch < NCH; ch++) s += g_part[(ch * B_ + b) * E_ + e];
    outa[b * E_ + e] = s;
}

// ---------------- launch ----------------
extern "C" void kernel_launch(void* const* d_in, const int* in_sizes, int n_in,
                              void* d_out, int out_size) {
    (void)in_sizes; (void)n_in; (void)out_size;
    const float* hid  = (const float*)d_in[0];  // (B, R)
    const float* mem  = (const float*)d_in[1];  // (B, T, E)
    const float* aw   = (const float*)d_in[2];  // (B, 2, T)
    const int*   mask = (const int*)d_in[3];    // (B, T)
    const float* Wq   = (const float*)d_in[4];  // (R, A)
    const float* Wm   = (const float*)d_in[5];  // (E, A)
    const float* cw   = (const float*)d_in[6];  // (F, 2, K)
    const float* Wl   = (const float*)d_in[7];  // (F, A)
    const float* vw   = (const float*)d_in[8];  // (A,)
    const float* vb   = (const float*)d_in[9];  // (1,)

    float* out      = (float*)d_out;
    float* out_attn = out;              // (B, E)
    float* out_w    = out + B_ * E_;    // (B, T)

    k_pq<<<B_, 128>>>(hid, Wq);
    k_wcat<<<KTOT, 128>>>(Wm, cw, Wl);
    dim3 gm(T_ / TT, B_);
    k_main<<<gm, 128>>>(mem, aw, mask, vw, vb);
    k_softmax<<<B_, 256>>>(out_w);
    dim3 gg(NCH, B_);
    k_gemv<<<gg, E_>>>(mem);
    k_reduce<<<B_, E_>>>(out_attn);
}

// round 2
// speedup vs baseline: 4.6013x; 4.6013x over previous
#include <cuda_runtime.h>
#include <math.h>

// Problem constants
#define B_   64
#define T_   2048
#define E_   512
#define R_   1024
#define A_   128
#define F_   32
#define KW   31
#define PADW 15

#define KIM   62
#define KTOT  576
#define KC    16
#define NCHUNK (KTOT / KC)
#define TM    128            // t-tile per block
#define NCH   8
#define TCH   (T_ / NCH)

typedef unsigned long long u64;

// Scratch (device globals; no allocations allowed)
__device__ float g_pq[B_ * A_];
__device__ float g_Wcat[KTOT * A_];
__device__ float g_align[B_ * T_];
__device__ float g_part[NCH * B_ * E_];

// ---------------- packed f32x2 helpers ----------------
__device__ __forceinline__ u64 pack2(float x, float y) {
    u64 r; asm("mov.b64 %0, {%1, %2};" : "=l"(r) : "f"(x), "f"(y)); return r;
}
__device__ __forceinline__ void unpack2(u64 v, float& x, float& y) {
    asm("mov.b64 {%0, %1}, %2;" : "=f"(x), "=f"(y) : "l"(v));
}
__device__ __forceinline__ void ffma2(u64& d, u64 a, u64 b) {
    asm("fma.rn.f32x2 %0, %1, %2, %0;" : "+l"(d) : "l"(a), "l"(b));
}
// accurate-enough tanh: (e^{2x}-1)/(e^{2x}+1) via ex2.approx + rcp.approx (~1e-6 rel)
__device__ __forceinline__ float tanh_fast(float x) {
    float e;
    asm("ex2.approx.f32 %0, %1;" : "=f"(e) : "f"(x * 2.885390081777927f));
    float r;
    asm("rcp.approx.f32 %0, %1;" : "=f"(r) : "f"(e + 1.0f));
    return fmaf(-2.0f, r, 1.0f);
}

// ---------------- pq = attention_hidden @ W_query : (B, A) ----------------
__global__ void k_pq(const float* __restrict__ hid, const float* __restrict__ Wq) {
    __shared__ float sh[R_];
    int b = blockIdx.x, tid = threadIdx.x;
    for (int i = tid; i < R_; i += 128) sh[i] = hid[b * R_ + i];
    __syncthreads();
    float acc = 0.f;
#pragma unroll 8
    for (int r = 0; r < R_; r++) acc += sh[r] * Wq[r * A_ + tid];
    g_pq[b * A_ + tid] = acc;
}

// ------------- Wcat rows: [0,512)=W_memory, [512,574)=conv_w . W_loc, rest 0 -------------
__global__ void k_wcat(const float* __restrict__ Wm, const float* __restrict__ cw,
                       const float* __restrict__ Wl) {
    int row = blockIdx.x;  // 0..575
    int a = threadIdx.x;   // 0..127
    float v = 0.f;
    if (row < E_) {
        v = Wm[row * A_ + a];
    } else if (row < E_ + KIM) {
        int ck = row - E_;
        int c = ck / KW, k = ck - c * KW;
#pragma unroll
        for (int f = 0; f < F_; f++)
            v += cw[f * (2 * KW) + c * KW + k] * Wl[f * A_ + a];
    }
    g_Wcat[row * A_ + a] = v;
}

// ---------------- main fused kernel: energies -> alignments ----------------
// 256 threads, block tile 128t x 128a, per-thread micro-tile 8t x 8a (f32x2 over a).
// Double-buffered K-chunks of 16 with register prefetch.
__global__ void __launch_bounds__(256, 2)
k_main(const float* __restrict__ mem, const float* __restrict__ aw,
       const int* __restrict__ mask, const float* __restrict__ vw,
       const float* __restrict__ vb) {
    __shared__ float sMf[2][KC][TM];   // m tile, plain floats (t-contiguous)
    __shared__ u64   sWs[2][KC][64];   // W row as f32x2 pairs, bank-swizzled

    int tid = threadIdx.x;
    int b   = blockIdx.y;
    int tb  = blockIdx.x * TM;

    int tx = tid & 15;          // a-group: a0 = tx*8
    int ty = tid >> 4;          // t-group: t0 = ty*8
    int lt  = tid & 127;        // loader t-row
    int lk8 = (tid >> 7) << 3;  // loader k-offset (0 or 8)
    int wr = ty;                // loader W row within chunk
    int wc = tx << 2;           // loader W u64 col (4 u64 = 8 floats)
    int gw = wc >> 4;           // store-side swizzle group

    // compute-side swizzled W read bases (2 x ulonglong2)
    int g   = tx >> 2;
    int s01 = (((tx & 3) << 2) + ((g & 1) << 1)) & 15;
    int wb0 = (g << 4) + s01;
    int wb1 = (g << 4) + ((s01 + 2) & 15);

    const float* memB = mem + ((size_t)b * T_ + tb) * E_;
    const float* awB  = aw + (size_t)b * 2 * T_;

    u64 acc[8][4];
#pragma unroll
    for (int i = 0; i < 8; i++)
#pragma unroll
        for (int j = 0; j < 4; j++) acc[i][j] = 0ull;

    float pf[8];
    u64   pw[4];

#define LOADG(cc) do {                                                          \
    int c_ = (cc);                                                              \
    if (c_ < (E_ / KC)) {                                                       \
        const float4* p_ = (const float4*)(memB + (size_t)lt * E_ + c_ * KC + lk8); \
        float4 v0_ = p_[0], v1_ = p_[1];                                        \
        pf[0]=v0_.x; pf[1]=v0_.y; pf[2]=v0_.z; pf[3]=v0_.w;                     \
        pf[4]=v1_.x; pf[5]=v1_.y; pf[6]=v1_.z; pf[7]=v1_.w;                     \
    } else {                                                                    \
        _Pragma("unroll")                                                       \
        for (int j_ = 0; j_ < 8; j_++) {                                        \
            int ck_ = c_ * KC + lk8 + j_ - E_;                                  \
            float v_ = 0.f;                                                     \
            if (ck_ < KIM) {                                                    \
                int ci_ = (ck_ >= KW) ? 1 : 0;                                  \
                int kp_ = ck_ - ci_ * KW;                                       \
                int t_  = tb + lt + kp_ - PADW;                                 \
                if (t_ >= 0 && t_ < T_) v_ = awB[ci_ * T_ + t_];                \
            }                                                                   \
            pf[j_] = v_;                                                        \
        }                                                                       \
    }                                                                           \
    const u64* wp_ = (const u64*)(const void*)g_Wcat + ((size_t)c_ * KC + wr) * 64 + wc; \
    ulonglong2 wv0_ = *(const ulonglong2*)wp_;                                  \
    ulonglong2 wv1_ = *(const ulonglong2*)(wp_ + 2);                            \
    pw[0]=wv0_.x; pw[1]=wv0_.y; pw[2]=wv1_.x; pw[3]=wv1_.y;                     \
} while (0)

#define STOREB(bufi) do {                                                       \
    _Pragma("unroll")                                                           \
    for (int j_ = 0; j_ < 8; j_++) sMf[bufi][lk8 + j_][lt] = pf[j_];            \
    _Pragma("unroll")                                                           \
    for (int q_ = 0; q_ < 4; q_++) {                                            \
        int idx_ = wc + q_;                                                     \
        int sw_ = (gw << 4) | ((idx_ + ((gw & 1) << 1)) & 15);                  \
        sWs[bufi][wr][sw_] = pw[q_];                                            \
    }                                                                           \
} while (0)

    // prologue: chunk 0
    LOADG(0);
    STOREB(0);
    __syncthreads();

    for (int c = 0; c < NCHUNK; c++) {
        int cur = c & 1;
        if (c + 1 < NCHUNK) LOADG(c + 1);

        const float (*sMb)[TM] = sMf[cur];
        const u64  (*sWb)[64] = sWs[cur];
#pragma unroll
        for (int kk = 0; kk < KC; kk++) {
            const u64* mp = (const u64*)(const void*)&sMb[kk][ty << 3];
            ulonglong2 mA = *(const ulonglong2*)(mp);
            ulonglong2 mB = *(const ulonglong2*)(mp + 2);
            u64 md[8];
            {
                float x, y;
                unpack2(mA.x, x, y); md[0] = pack2(x, x); md[1] = pack2(y, y);
                unpack2(mA.y, x, y); md[2] = pack2(x, x); md[3] = pack2(y, y);
                unpack2(mB.x, x, y); md[4] = pack2(x, x); md[5] = pack2(y, y);
                unpack2(mB.y, x, y); md[6] = pack2(x, x); md[7] = pack2(y, y);
            }
            const u64* wrow = sWb[kk];
            ulonglong2 wA = *(const ulonglong2*)(wrow + wb0);
            ulonglong2 wB = *(const ulonglong2*)(wrow + wb1);
            u64 w0 = wA.x, w1 = wA.y, w2 = wB.x, w3 = wB.y;
#pragma unroll
            for (int i = 0; i < 8; i++) {
                ffma2(acc[i][0], md[i], w0);
                ffma2(acc[i][1], md[i], w1);
                ffma2(acc[i][2], md[i], w2);
                ffma2(acc[i][3], md[i], w3);
            }
        }
        __syncthreads();
        if (c + 1 < NCHUNK) {
            STOREB(cur ^ 1);
            __syncthreads();
        }
    }
#undef LOADG
#undef STOREB

    // ---- epilogue: +pq, tanh, dot v, reduce over a (16 lanes), mask ----
    float pq[8], vv[8];
    {
        const float4* pp = (const float4*)(g_pq + b * A_ + (tx << 3));
        float4 q0 = pp[0], q1 = pp[1];
        pq[0]=q0.x; pq[1]=q0.y; pq[2]=q0.z; pq[3]=q0.w;
        pq[4]=q1.x; pq[5]=q1.y; pq[6]=q1.z; pq[7]=q1.w;
        const float4* vp = (const float4*)(vw + (tx << 3));
        float4 v0 = vp[0], v1 = vp[1];
        vv[0]=v0.x; vv[1]=v0.y; vv[2]=v0.z; vv[3]=v0.w;
        vv[4]=v1.x; vv[5]=v1.y; vv[6]=v1.z; vv[7]=v1.w;
    }
    float en[8];
#pragma unroll
    for (int i = 0; i < 8; i++) {
        float e = 0.f;
#pragma unroll
        for (int j = 0; j < 4; j++) {
            float x, y;
            unpack2(acc[i][j], x, y);
            e += vv[2 * j]     * tanh_fast(x + pq[2 * j]);
            e += vv[2 * j + 1] * tanh_fast(y + pq[2 * j + 1]);
        }
        en[i] = e;
    }
#pragma unroll
    for (int off = 8; off >= 1; off >>= 1)
#pragma unroll
        for (int i = 0; i < 8; i++)
            en[i] += __shfl_xor_sync(0xffffffffu, en[i], off);

    if (tx == 0) {
        float bb = vb[0];
#pragma unroll
        for (int i = 0; i < 8; i++) {
            int t = tb + (ty << 3) + i;
            float al = en[i] + bb;
            if (mask[b * T_ + t]) al += -1e25f;
            g_align[b * T_ + t] = al;
        }
    }
}

// ---------------- softmax over T per batch -> attention_weights ----------------
__global__ void k_softmax(float* __restrict__ outw) {
    __shared__ float sE[T_];
    __shared__ float red[256];
    int b = blockIdx.x, tid = threadIdx.x;
    float mx = -3.4e38f;
    for (int i = tid; i < T_; i += 256) {
        float v = g_align[b * T_ + i];
        sE[i] = v;
        mx = fmaxf(mx, v);
    }
    red[tid] = mx;
    __syncthreads();
    for (int s = 128; s > 0; s >>= 1) {
        if (tid < s) red[tid] = fmaxf(red[tid], red[tid + s]);
        __syncthreads();
    }
    mx = red[0];
    __syncthreads();
    float sum = 0.f;
    for (int i = tid; i < T_; i += 256) {
        float ev = expf(sE[i] - mx);
        sE[i] = ev;
        sum += ev;
    }
    red[tid] = sum;
    __syncthreads();
    for (int s = 128; s > 0; s >>= 1) {
        if (tid < s) red[tid] += red[tid + s];
        __syncthreads();
    }
    float inv = 1.f / red[0];
    for (int i = tid; i < T_; i += 256) outw[b * T_ + i] = sE[i] * inv;
}

// ---------------- output GEMV: partials over T chunks ----------------
__global__ void k_gemv(const float* __restrict__ mem) {
    __shared__ float sA[TCH];
    int ch = blockIdx.x, b = blockIdx.y, e = threadIdx.x;
    for (int i = e; i < TCH; i += E_) sA[i] = g_align[b * T_ + ch * TCH + i];
    __syncthreads();
    const float* mp = mem + ((size_t)b * T_ + (size_t)ch * TCH) * E_ + e;
    float acc = 0.f;
#pragma unroll 8
    for (int t = 0; t < TCH; t++) acc += sA[t] * mp[(size_t)t * E_];
    g_part[(ch * B_ + b) * E_ + e] = acc;
}

__global__ void k_reduce(float* __restrict__ outa) {
    int b = blockIdx.x, e = threadIdx.x;
    float s = 0.f;
#pragma unroll
    for (int ch = 0; ch < NCH; ch++) s += g_part[(ch * B_ + b) * E_ + e];
    outa[b * E_ + e] = s;
}

// ---------------- launch ----------------
extern "C" void kernel_launch(void* const* d_in, const int* in_sizes, int n_in,
                              void* d_out, int out_size) {
    (void)in_sizes; (void)n_in; (void)out_size;
    const float* hid  = (const float*)d_in[0];  // (B, R)
    const float* mem  = (const float*)d_in[1];  // (B, T, E)
    const float* aw   = (const float*)d_in[2];  // (B, 2, T)
    const int*   mask = (const int*)d_in[3];    // (B, T)
    const float* Wq   = (const float*)d_in[4];  // (R, A)
    const float* Wm   = (const float*)d_in[5];  // (E, A)
    const float* cw   = (const float*)d_in[6];  // (F, 2, K)
    const float* Wl   = (const float*)d_in[7];  // (F, A)
    const float* vw   = (const float*)d_in[8];  // (A,)
    const float* vb   = (const float*)d_in[9];  // (1,)

    float* out      = (float*)d_out;
    float* out_attn = out;              // (B, E)
    float* out_w    = out + B_ * E_;    // (B, T)

    k_pq<<<B_, 128>>>(hid, Wq);
    k_wcat<<<KTOT, 128>>>(Wm, cw, Wl);
    dim3 gm(T_ / TM, B_);
    k_main<<<gm, 256>>>(mem, aw, mask, vw, vb);
    k_softmax<<<B_, 256>>>(out_w);
    dim3 gg(NCH, B_);
    k_gemv<<<gg, E_>>>(mem);
    k_reduce<<<B_, E_>>>(out_attn);
}

// round 6
// speedup vs baseline: 6.7126x; 1.4589x over previous
#include <cuda_runtime.h>
#include <cuda_bf16.h>
#include <math.h>
#include <stdint.h>

// Problem constants
#define B_   64
#define T_   2048
#define E_   512
#define R_   1024
#define A_   128
#define F_   32
#define KW   31
#define PADW 15
#define KIM  62
#define KTOT 576
#define KC2  64          // original-K per chunk
#define NCK  9           // 576/64
#define TM   128         // t rows per block
#define NPART 16         // T_/TM

typedef unsigned long long u64;

// Scratch (device globals; no allocations allowed)
__device__ float g_pq[B_ * A_];
__device__ __align__(16) __nv_bfloat16 g_Whi[A_ * KTOT];  // W^T hi split: [a][k]
__device__ __align__(16) __nv_bfloat16 g_Wlo[A_ * KTOT];  // W^T lo split
__device__ float g_align[B_ * T_];
__device__ float g_part[NPART * B_ * E_];

// ---- dynamic smem layout ----
#define OFF_AHI 0
#define OFF_ALO 16384
#define OFF_BHI 32768
#define OFF_BLO 49152
#define OFF_PQ  65536
#define OFF_V   66048
#define OFF_AL  66560
#define OFF_EN  67072            // 4 x 128 x 4B = 2048
#define SMEM_SZ 69120

__device__ __forceinline__ uint32_t smem_u32(const void* p) {
    uint32_t a;
    asm("{ .reg .u64 t; cvta.to.shared.u64 t, %1; cvt.u32.u64 %0, t; }" : "=r"(a) : "l"(p));
    return a;
}
// accurate tanh: 1 - 2/(e^{2x}+1) via ex2.approx + rcp.approx (~1e-6 rel)
__device__ __forceinline__ float tanh_fast(float x) {
    float e;
    asm("ex2.approx.f32 %0, %1;" : "=f"(e) : "f"(x * 2.885390081777927f));
    float r;
    asm("rcp.approx.f32 %0, %1;" : "=f"(r) : "f"(e + 1.0f));
    return fmaf(-2.0f, r, 1.0f);
}

__device__ __forceinline__ void ldsm4(uint32_t addr, uint32_t& r0, uint32_t& r1,
                                      uint32_t& r2, uint32_t& r3) {
    asm volatile("ldmatrix.sync.aligned.m8n8.x4.shared.b16 {%0,%1,%2,%3}, [%4];"
                 : "=r"(r0), "=r"(r1), "=r"(r2), "=r"(r3) : "r"(addr));
}
__device__ __forceinline__ void mma16816(float* c, const uint32_t* a, uint32_t b0, uint32_t b1) {
    asm volatile(
        "mma.sync.aligned.m16n8k16.row.col.f32.bf16.bf16.f32 "
        "{%0,%1,%2,%3}, {%4,%5,%6,%7}, {%8,%9}, {%0,%1,%2,%3};"
        : "+f"(c[0]), "+f"(c[1]), "+f"(c[2]), "+f"(c[3])
        : "r"(a[0]), "r"(a[1]), "r"(a[2]), "r"(a[3]), "r"(b0), "r"(b1));
}
__device__ __forceinline__ uint32_t cvt_bf2(float hi_elem, float lo_elem) {
    uint32_t r;
    asm("cvt.rn.bf16x2.f32 %0, %1, %2;" : "=r"(r) : "f"(hi_elem), "f"(lo_elem));
    return r;  // low half = lo_elem, high half = hi_elem
}

// ---------------- pq = attention_hidden @ W_query : (B, A) ----------------
__global__ void k_pq(const float* __restrict__ hid, const float* __restrict__ Wq) {
    __shared__ float sh[R_];
    int b = blockIdx.x, tid = threadIdx.x;
    for (int i = tid; i < R_; i += 128) sh[i] = hid[b * R_ + i];
    __syncthreads();
    float acc = 0.f;
#pragma unroll 8
    for (int r = 0; r < R_; r++) acc += sh[r] * Wq[r * A_ + tid];
    g_pq[b * A_ + tid] = acc;
}

// ---- Wcat^T bf16 split: k<512 = W_memory, 512..573 = conv.W_loc, rest 0 ----
__global__ void k_wcat(const float* __restrict__ Wm, const float* __restrict__ cw,
                       const float* __restrict__ Wl) {
    int row = blockIdx.x;  // k: 0..575
    int a = threadIdx.x;   // 0..127
    float v = 0.f;
    if (row < E_) {
        v = Wm[row * A_ + a];
    } else if (row < E_ + KIM) {
        int ck = row - E_;
        int c = ck / KW, k = ck - c * KW;
#pragma unroll
        for (int f = 0; f < F_; f++)
            v += cw[f * (2 * KW) + c * KW + k] * Wl[f * A_ + a];
    }
    __nv_bfloat16 h = __float2bfloat16_rn(v);
    float lo = v - __bfloat162float(h);
    g_Whi[a * KTOT + row] = h;
    g_Wlo[a * KTOT + row] = __float2bfloat16_rn(lo);
}

// ---------------- main: mma.sync bf16 3-split GEMM + epilogue + fused GEMV ----------------
__global__ void __launch_bounds__(256, 2)
k_main(const float* __restrict__ mem, const float* __restrict__ aw,
       const int* __restrict__ mask, const float* __restrict__ vw,
       const float* __restrict__ vb) {
    extern __shared__ char smc[];
    uint32_t sb = smem_u32(smc);
    int tid = threadIdx.x;
    int l = tid & 31, w = tid >> 5;
    int wa = w & 3, wt = w >> 2;      // warp tile: 64t (wt) x 32a (wa)
    int b = blockIdx.y, tb = blockIdx.x * TM;

    if (tid < A_) {
        ((float*)(smc + OFF_PQ))[tid] = g_pq[b * A_ + tid];
        ((float*)(smc + OFF_V))[tid]  = vw[tid];
    }

    float acc[4][4][4];
#pragma unroll
    for (int i = 0; i < 4; i++)
#pragma unroll
        for (int j = 0; j < 4; j++)
#pragma unroll
            for (int k = 0; k < 4; k++) acc[i][j][k] = 0.f;

    const float* memB = mem + ((size_t)b * T_ + tb) * E_;
    const float* awB  = aw + (size_t)b * 2 * T_;

    // conversion mapping: 256 threads -> 128 rows x 2 k-halves of 32
    int crow = tid >> 1, chalf = (tid & 1) * 32;
    uint32_t cRowBase = (uint32_t)crow * 128u;
    int cSwz = crow & 7;

    // ldmatrix lane constants
    int rowA = wt * 64 + (l & 15);            // + mi*16
    uint32_t aRowBase = (uint32_t)rowA * 128u;
    int aSwz = rowA & 7;                       // invariant under +mi*16
    int kpA = (l >> 4) & 1;
    int nB = wa * 32 + ((l & 16) >> 1) + (l & 7);  // + nj2*16
    uint32_t bRowBase = (uint32_t)nB * 128u;
    int bSwz = l & 7;
    int kpB = (l >> 3) & 1;

#pragma unroll 1
    for (int c = 0; c < NCK; c++) {
        __syncthreads();   // previous compute done before overwrite
        // ---- A convert: 32 fp32 -> bf16 hi/lo, swizzled STS ----
        float xs[32];
        if (c < 8) {
            const float4* src = (const float4*)(memB + (size_t)crow * E_ + c * KC2 + chalf);
#pragma unroll
            for (int q = 0; q < 8; q++) {
                float4 v = src[q];
                xs[q * 4 + 0] = v.x; xs[q * 4 + 1] = v.y;
                xs[q * 4 + 2] = v.z; xs[q * 4 + 3] = v.w;
            }
        } else {
#pragma unroll
            for (int j = 0; j < 32; j++) {
                int kk = chalf + j;
                float v = 0.f;
                if (kk < KIM) {
                    int ci = (kk >= KW) ? 1 : 0;
                    int kp = kk - ci * KW;
                    int tg = tb + crow + kp - PADW;
                    if (tg >= 0 && tg < T_) v = awB[ci * T_ + tg];
                }
                xs[j] = v;
            }
        }
#pragma unroll
        for (int u = 0; u < 4; u++) {   // 16B unit = 8 values
            uint32_t hw[4], lw[4];
#pragma unroll
            for (int p = 0; p < 4; p++) {
                float x0 = xs[u * 8 + 2 * p], x1 = xs[u * 8 + 2 * p + 1];
                uint32_t h = cvt_bf2(x1, x0);
                float f0 = __uint_as_float(h << 16);
                float f1 = __uint_as_float(h & 0xffff0000u);
                lw[p] = cvt_bf2(x1 - f1, x0 - f0);
                hw[p] = h;
            }
            int q = (chalf >> 3) + u;
            uint32_t off = cRowBase + (uint32_t)((q ^ cSwz) << 4);
            *(uint4*)(smc + OFF_AHI + off) = make_uint4(hw[0], hw[1], hw[2], hw[3]);
            *(uint4*)(smc + OFF_ALO + off) = make_uint4(lw[0], lw[1], lw[2], lw[3]);
        }
        // ---- B copy: 128 a-rows x 64 k, hi/lo, swizzled ----
#pragma unroll
        for (int i = 0; i < 4; i++) {
            int idx = i * 256 + tid;
            int n = idx >> 3, q = idx & 7;
            uint32_t off = (uint32_t)n * 128u + (uint32_t)(((q ^ (n & 7)) << 4));
            const char* sh = (const char*)g_Whi + (size_t)n * (KTOT * 2) + c * 128 + q * 16;
            const char* sl = (const char*)g_Wlo + (size_t)n * (KTOT * 2) + c * 128 + q * 16;
            *(uint4*)(smc + OFF_BHI + off) = *(const uint4*)sh;
            *(uint4*)(smc + OFF_BLO + off) = *(const uint4*)sl;
        }
        __syncthreads();

        // ---- compute: pass1 Bhi x (Ahi + Alo), pass2 Blo x Ahi ----
#pragma unroll
        for (int s = 0; s < 4; s++) {
            uint32_t bf[8];
            uint32_t kbB = (uint32_t)((((2 * s + kpB) ^ bSwz) << 4));
            ldsm4(sb + OFF_BHI + bRowBase + kbB,          bf[0], bf[1], bf[2], bf[3]);
            ldsm4(sb + OFF_BHI + bRowBase + 2048u + kbB,  bf[4], bf[5], bf[6], bf[7]);
            uint32_t kbA = (uint32_t)((((2 * s + kpA) ^ aSwz) << 4));
#pragma unroll
            for (int mi = 0; mi < 4; mi++) {
                uint32_t af[4];
                ldsm4(sb + OFF_AHI + aRowBase + mi * 2048u + kbA, af[0], af[1], af[2], af[3]);
                mma16816(acc[mi][0], af, bf[0], bf[1]);
                mma16816(acc[mi][1], af, bf[2], bf[3]);
                mma16816(acc[mi][2], af, bf[4], bf[5]);
                mma16816(acc[mi][3], af, bf[6], bf[7]);
                ldsm4(sb + OFF_ALO + aRowBase + mi * 2048u + kbA, af[0], af[1], af[2], af[3]);
                mma16816(acc[mi][0], af, bf[0], bf[1]);
                mma16816(acc[mi][1], af, bf[2], bf[3]);
                mma16816(acc[mi][2], af, bf[4], bf[5]);
                mma16816(acc[mi][3], af, bf[6], bf[7]);
            }
        }
#pragma unroll
        for (int s = 0; s < 4; s++) {
            uint32_t bf[8];
            uint32_t kbB = (uint32_t)((((2 * s + kpB) ^ bSwz) << 4));
            ldsm4(sb + OFF_BLO + bRowBase + kbB,          bf[0], bf[1], bf[2], bf[3]);
            ldsm4(sb + OFF_BLO + bRowBase + 2048u + kbB,  bf[4], bf[5], bf[6], bf[7]);
            uint32_t kbA = (uint32_t)((((2 * s + kpA) ^ aSwz) << 4));
#pragma unroll
            for (int mi = 0; mi < 4; mi++) {
                uint32_t af[4];
                ldsm4(sb + OFF_AHI + aRowBase + mi * 2048u + kbA, af[0], af[1], af[2], af[3]);
                mma16816(acc[mi][0], af, bf[0], bf[1]);
                mma16816(acc[mi][1], af, bf[2], bf[3]);
                mma16816(acc[mi][2], af, bf[4], bf[5]);
                mma16816(acc[mi][3], af, bf[6], bf[7]);
            }
        }
    }

    // ---- epilogue: en[t] = sum_a v[a] * tanh(D[t,a] + pq[a]) ----
    {
        const float* sPQ = (const float*)(smc + OFF_PQ);
        const float* sV  = (const float*)(smc + OFF_V);
        float* sEn = (float*)(smc + OFF_EN);   // [4 wa][128 t]
#pragma unroll
        for (int mi = 0; mi < 4; mi++) {
            float en1 = 0.f, en2 = 0.f;
#pragma unroll
            for (int nj = 0; nj < 4; nj++) {
                int a0 = wa * 32 + nj * 8 + 2 * (l & 3);
                float v0 = sV[a0], v1 = sV[a0 + 1];
                float q0 = sPQ[a0], q1 = sPQ[a0 + 1];
                en1 += v0 * tanh_fast(acc[mi][nj][0] + q0) + v1 * tanh_fast(acc[mi][nj][1] + q1);
                en2 += v0 * tanh_fast(acc[mi][nj][2] + q0) + v1 * tanh_fast(acc[mi][nj][3] + q1);
            }
            en1 += __shfl_xor_sync(0xffffffffu, en1, 1);
            en1 += __shfl_xor_sync(0xffffffffu, en1, 2);
            en2 += __shfl_xor_sync(0xffffffffu, en2, 1);
            en2 += __shfl_xor_sync(0xffffffffu, en2, 2);
            if ((l & 3) == 0) {
                int r1 = wt * 64 + mi * 16 + (l >> 2);
                sEn[wa * TM + r1] = en1;
                sEn[wa * TM + r1 + 8] = en2;
            }
        }
    }
    __syncthreads();
    if (tid < TM) {
        float* sEn = (float*)(smc + OFF_EN);
        float al = sEn[tid] + sEn[TM + tid] + sEn[2 * TM + tid] + sEn[3 * TM + tid] + vb[0];
        if (mask[b * T_ + tb + tid]) al += -1e25f;
        g_align[b * T_ + tb + tid] = al;
        ((float*)(smc + OFF_AL))[tid] = al;
    }
    __syncthreads();

    // ---- fused output GEMV partials: part[e] = sum_t align[t] * mem[b,tb+t,e] ----
    {
        const float* sAl = (const float*)(smc + OFF_AL);
        int e2 = tid * 2;
        float a0 = 0.f, a1 = 0.f;
        const float* mp = memB + e2;
#pragma unroll 8
        for (int t = 0; t < TM; t++) {
            float al = sAl[t];
            float2 m = *(const float2*)(mp + (size_t)t * E_);
            a0 = fmaf(al, m.x, a0);
            a1 = fmaf(al, m.y, a1);
        }
        float2 res; res.x = a0; res.y = a1;
        *(float2*)(g_part + (size_t)blockIdx.x * (B_ * E_) + b * E_ + e2) = res;
    }
}

// ---------------- softmax over T per batch -> attention_weights ----------------
__global__ void k_softmax(float* __restrict__ outw) {
    __shared__ float sE[T_];
    __shared__ float red[256];
    int b = blockIdx.x, tid = threadIdx.x;
    float mx = -3.4e38f;
    for (int i = tid; i < T_; i += 256) {
        float v = g_align[b * T_ + i];
        sE[i] = v;
        mx = fmaxf(mx, v);
    }
    red[tid] = mx;
    __syncthreads();
    for (int s = 128; s > 0; s >>= 1) {
        if (tid < s) red[tid] = fmaxf(red[tid], red[tid + s]);
        __syncthreads();
    }
    mx = red[0];
    __syncthreads();
    float sum = 0.f;
    for (int i = tid; i < T_; i += 256) {
        float ev = expf(sE[i] - mx);
        sE[i] = ev;
        sum += ev;
    }
    red[tid] = sum;
    __syncthreads();
    for (int s = 128; s > 0; s >>= 1) {
        if (tid < s) red[tid] += red[tid + s];
        __syncthreads();
    }
    float inv = 1.f / red[0];
    for (int i = tid; i < T_; i += 256) outw[b * T_ + i] = sE[i] * inv;
}

// ---------------- reduce GEMV partials ----------------
__global__ void k_reduce(float* __restrict__ outa) {
    int b = blockIdx.x, e = threadIdx.x;
    float s = 0.f;
#pragma unroll
    for (int p = 0; p < NPART; p++) s += g_part[(size_t)p * (B_ * E_) + b * E_ + e];
    outa[b * E_ + e] = s;
}

// ---------------- launch ----------------
extern "C" void kernel_launch(void* const* d_in, const int* in_sizes, int n_in,
                              void* d_out, int out_size) {
    (void)in_sizes; (void)n_in; (void)out_size;
    const float* hid  = (const float*)d_in[0];  // (B, R)
    const float* mem  = (const float*)d_in[1];  // (B, T, E)
    const float* aw   = (const float*)d_in[2];  // (B, 2, T)
    const int*   mask = (const int*)d_in[3];    // (B, T)
    const float* Wq   = (const float*)d_in[4];  // (R, A)
    const float* Wm   = (const float*)d_in[5];  // (E, A)
    const float* cw   = (const float*)d_in[6];  // (F, 2, K)
    const float* Wl   = (const float*)d_in[7];  // (F, A)
    const float* vw   = (const float*)d_in[8];  // (A,)
    const float* vb   = (const float*)d_in[9];  // (1,)

    float* out      = (float*)d_out;
    float* out_attn = out;              // (B, E)
    float* out_w    = out + B_ * E_;    // (B, T)

    static int configured = 0;
    if (!configured) {
        cudaFuncSetAttribute(k_main, cudaFuncAttributeMaxDynamicSharedMemorySize, SMEM_SZ);
        configured = 1;
    }

    k_pq<<<B_, 128>>>(hid, Wq);
    k_wcat<<<KTOT, 128>>>(Wm, cw, Wl);
    dim3 gm(T_ / TM, B_);
    k_main<<<gm, 256, SMEM_SZ>>>(mem, aw, mask, vw, vb);
    k_softmax<<<B_, 256>>>(out_w);
    k_reduce<<<B_, E_>>>(out_attn);
}